// round 8
// baseline (speedup 1.0000x reference)
#include <cuda_runtime.h>
#include <cuda_bf16.h>
#include <cstdint>

// ============================================================================
// Problem constants
// ============================================================================
static constexpr int BROWS = 16384;   // B*L rows of H
static constexpr int DK    = 1024;    // K (hidden dim)
static constexpr int NPAD  = 1024;    // padded N: dep 0..499 | 0 | head 512..1011 | 0
static constexpr int MLP   = 500;

static constexpr int BM = 128, BN = 128, BK = 32;
static constexpr int NIT = DK / BK;   // 32
static constexpr int STAGES = 4;

// Scratch (device globals; no allocation allowed)
__device__ __align__(16) __nv_bfloat16 g_Ahi[BROWS * DK];   // 32 MB
__device__ __align__(16) __nv_bfloat16 g_Alo[BROWS * DK];   // 32 MB
__device__ __align__(16) __nv_bfloat16 g_Bhi[NPAD * DK];
__device__ __align__(16) __nv_bfloat16 g_Blo[NPAD * DK];
__device__ __align__(16) float2 g_part[BROWS * 8];    // [row][ntile] partial (s0,s1)
__device__ __align__(16) float2 g_dpack[BROWS];       // dep + bc
__device__ __align__(16) float2 g_hpack[BROWS];       // head
__device__ __align__(16) float g_wc0[NPAD];
__device__ __align__(16) float g_wc1[NPAD];
__device__ __align__(16) float g_bias[NPAD];

// ============================================================================
// Helpers
// ============================================================================
__device__ __forceinline__ uint32_t smem_u32(const void* p) {
    uint32_t a;
    asm("{ .reg .u64 t; cvta.to.shared.u64 t, %1; cvt.u32.u64 %0, t; }" : "=r"(a) : "l"(p));
    return a;
}
__device__ __forceinline__ void ldsm_x4(uint32_t* r, uint32_t addr) {
    asm volatile("ldmatrix.sync.aligned.m8n8.x4.shared.b16 {%0,%1,%2,%3}, [%4];"
                 : "=r"(r[0]), "=r"(r[1]), "=r"(r[2]), "=r"(r[3]) : "r"(addr));
}
__device__ __forceinline__ void mma_16816(float* c, const uint32_t* a, const uint32_t* b) {
    asm volatile(
        "mma.sync.aligned.m16n8k16.row.col.f32.bf16.bf16.f32 "
        "{%0,%1,%2,%3}, {%4,%5,%6,%7}, {%8,%9}, {%0,%1,%2,%3};"
        : "+f"(c[0]), "+f"(c[1]), "+f"(c[2]), "+f"(c[3])
        : "r"(a[0]), "r"(a[1]), "r"(a[2]), "r"(a[3]), "r"(b[0]), "r"(b[1]));
}
__device__ __forceinline__ uint32_t pack_bf16x2(__nv_bfloat16 lo, __nv_bfloat16 hi) {
    return ((uint32_t)__bfloat16_as_ushort(hi) << 16) | __bfloat16_as_ushort(lo);
}
#define CP16(dst, src) \
    asm volatile("cp.async.cg.shared.global [%0], [%1], 16;" :: "r"(dst), "l"(src) : "memory")
#define CP_COMMIT() asm volatile("cp.async.commit_group;" ::: "memory")
#define CP_WAIT(n)  asm volatile("cp.async.wait_group %0;" :: "n"(n) : "memory")

// XOR-swizzled byte offset for 16B chunk c (0..3) in row r (64B rows)
__device__ __forceinline__ uint32_t swz(int r, int c) {
    return (uint32_t)(r * 64 + ((c ^ ((r >> 1) & 3)) << 4));
}

// ============================================================================
// Prep: transpose+pad+split weights to bf16 hi/lo, fuse wc/bias
// ============================================================================
__global__ __launch_bounds__(256) void prep_kernel(
    const float* __restrict__ Wd, const float* __restrict__ Wh,
    const float* __restrict__ bd, const float* __restrict__ bh,
    const float* __restrict__ Wc)
{
    const int n  = blockIdx.x;
    const int k0 = threadIdx.x * 4;
    __nv_bfloat16 hi[4], lo[4];
    #pragma unroll
    for (int i = 0; i < 4; ++i) {
        float w = 0.f;
        if (n < MLP)                        w = __ldg(Wd + (k0 + i) * MLP + n);
        else if (n >= 512 && n < 512 + MLP) w = __ldg(Wh + (k0 + i) * MLP + (n - 512));
        hi[i] = __float2bfloat16(w);
        lo[i] = __float2bfloat16(w - __bfloat162float(hi[i]));
    }
    uint2 vh = make_uint2(pack_bf16x2(hi[0], hi[1]), pack_bf16x2(hi[2], hi[3]));
    uint2 vl = make_uint2(pack_bf16x2(lo[0], lo[1]), pack_bf16x2(lo[2], lo[3]));
    *reinterpret_cast<uint2*>(g_Bhi + n * DK + k0) = vh;
    *reinterpret_cast<uint2*>(g_Blo + n * DK + k0) = vl;

    if (threadIdx.x == 0) {
        float c0 = 0.f, c1 = 0.f, bb = 0.f;
        if (n < MLP)                      { c0 = Wc[n*2]; c1 = Wc[n*2+1]; bb = bd[n]; }
        else if (n >= 512 && n < 512+MLP) { int m = n - 512 + MLP;
                                            c0 = Wc[m*2]; c1 = Wc[m*2+1]; bb = bh[n-512]; }
        g_wc0[n] = c0; g_wc1[n] = c1; g_bias[n] = bb;
    }
}

// ============================================================================
// A-split: H f32 -> Ahi/Alo bf16 (coalesced stream)
// ============================================================================
__global__ __launch_bounds__(256) void asplit_kernel(const float4* __restrict__ Hv)
{
    const int idx = blockIdx.x * 256 + threadIdx.x;   // float4 index
    const float4 v = __ldg(Hv + idx);
    const __nv_bfloat16 h0 = __float2bfloat16(v.x);
    const __nv_bfloat16 h1 = __float2bfloat16(v.y);
    const __nv_bfloat16 h2 = __float2bfloat16(v.z);
    const __nv_bfloat16 h3 = __float2bfloat16(v.w);
    uint2 hv = make_uint2(pack_bf16x2(h0, h1), pack_bf16x2(h2, h3));
    uint2 lv = make_uint2(
        pack_bf16x2(__float2bfloat16(v.x - __bfloat162float(h0)),
                    __float2bfloat16(v.y - __bfloat162float(h1))),
        pack_bf16x2(__float2bfloat16(v.z - __bfloat162float(h2)),
                    __float2bfloat16(v.w - __bfloat162float(h3))));
    reinterpret_cast<uint2*>(g_Ahi)[idx] = hv;
    reinterpret_cast<uint2*>(g_Alo)[idx] = lv;
}

// ============================================================================
// GEMM: 512 threads (4 warps/SMSP), 4-stage cp.async pipeline,
// bf16 split (Ah*Bh + Ah*Bl + Al*Bh), smem-reduced epilogue, no atomics
// ============================================================================
static constexpr int SUB_AHI = 0, SUB_ALO = 8192, SUB_BHI = 16384, SUB_BLO = 24576;
static constexpr int STAGE_B  = 32768;                // 4 x 8KB
static constexpr int SMEM_BYTES = STAGES * STAGE_B;   // 128 KB dynamic

__global__ __launch_bounds__(512, 1) void gemm_kernel()
{
    extern __shared__ char smem[];
    __shared__ float2 s_red[BM];                       // 1 KB static
    const uint32_t sb = smem_u32(smem);

    const int tid = threadIdx.x;
    const int l   = tid & 31;
    const int wid = tid >> 5;        // 0..15
    const int wm  = wid & 1;         // m half (rows wm*64..+63)
    const int wn  = wid >> 1;        // 0..7 (cols wn*16..+15)
    const int nbase = blockIdx.x * BN;
    const int rbase = blockIdx.y * BM;

    // ---- cp.async geometry: 1 chunk per sub-tile per thread ----
    const int cpRow = tid >> 2;
    const int cpC   = tid & 3;
    const uint32_t cpS = swz(cpRow, cpC);
    const size_t gA = (size_t)(rbase + cpRow) * 2048 + cpC * 16;  // bytes
    const size_t gB = (size_t)(nbase + cpRow) * 2048 + cpC * 16;
    const char* pAhi = reinterpret_cast<const char*>(g_Ahi);
    const char* pAlo = reinterpret_cast<const char*>(g_Alo);
    const char* pBhi = reinterpret_cast<const char*>(g_Bhi);
    const char* pBlo = reinterpret_cast<const char*>(g_Blo);

    auto issue = [&](int slice) {
        const uint32_t stg = sb + (slice % STAGES) * STAGE_B;
        const size_t ko = (size_t)slice * 64;
        CP16(stg + SUB_AHI + cpS, pAhi + gA + ko);
        CP16(stg + SUB_ALO + cpS, pAlo + gA + ko);
        CP16(stg + SUB_BHI + cpS, pBhi + gB + ko);
        CP16(stg + SUB_BLO + cpS, pBlo + gB + ko);
        CP_COMMIT();
    };

    // ---- ldmatrix geometry ----
    uint32_t aOff[4], aXor[4];
    #pragma unroll
    for (int mt = 0; mt < 4; ++mt) {
        const int r = wm * 64 + mt * 16 + (l & 15);
        aOff[mt] = (uint32_t)(r * 64);
        aXor[mt] = (uint32_t)((r >> 1) & 3);
    }
    const int cA = l >> 4;              // 0/1
    const int rB = wn * 16 + (l & 7) + ((l >> 4) << 3);
    const uint32_t bOff = (uint32_t)(rB * 64);
    const uint32_t bXor = (uint32_t)((rB >> 1) & 3);
    const int cB = (l & 8) ? 1 : 0;

    float acc[4][2][4];   // [mt][n8][frag]
    #pragma unroll
    for (int a = 0; a < 4; ++a)
        #pragma unroll
        for (int b = 0; b < 2; ++b)
            #pragma unroll
            for (int c = 0; c < 4; ++c) acc[a][b][c] = 0.f;

    #pragma unroll
    for (int s = 0; s < STAGES - 1; ++s) issue(s);

    for (int kt = 0; kt < NIT; ++kt) {
        if (kt + STAGES - 1 < NIT) issue(kt + STAGES - 1);
        else CP_COMMIT();
        CP_WAIT(STAGES - 1);
        __syncthreads();

        const uint32_t stg = sb + (kt % STAGES) * STAGE_B;
        #pragma unroll
        for (int s = 0; s < 2; ++s) {
            uint32_t ah[4][4], al[4][4], bh[4], bl[4];
            const int ca = s * 2 + cA;
            const int cb = s * 2 + cB;
            #pragma unroll
            for (int mt = 0; mt < 4; ++mt) {
                const uint32_t off = aOff[mt] + (((uint32_t)ca ^ aXor[mt]) << 4);
                ldsm_x4(ah[mt], stg + SUB_AHI + off);
                ldsm_x4(al[mt], stg + SUB_ALO + off);
            }
            {
                const uint32_t off = bOff + (((uint32_t)cb ^ bXor) << 4);
                ldsm_x4(bh, stg + SUB_BHI + off);
                ldsm_x4(bl, stg + SUB_BLO + off);
            }
            // Pass 1: Ah * Bh
            #pragma unroll
            for (int mt = 0; mt < 4; ++mt) {
                mma_16816(acc[mt][0], ah[mt], &bh[0]);
                mma_16816(acc[mt][1], ah[mt], &bh[2]);
            }
            // Pass 2: Ah * Bl
            #pragma unroll
            for (int mt = 0; mt < 4; ++mt) {
                mma_16816(acc[mt][0], ah[mt], &bl[0]);
                mma_16816(acc[mt][1], ah[mt], &bl[2]);
            }
            // Pass 3: Al * Bh
            #pragma unroll
            for (int mt = 0; mt < 4; ++mt) {
                mma_16816(acc[mt][0], al[mt], &bh[0]);
                mma_16816(acc[mt][1], al[mt], &bh[2]);
            }
        }
        __syncthreads();
    }

    // ---- Epilogue: bias + LeakyReLU + dot wc; smem reduce; plain stores ----
    if (tid < BM) s_red[tid] = make_float2(0.f, 0.f);
    __syncthreads();

    const int quad = l >> 2, qlane = l & 3;
    #pragma unroll
    for (int mt = 0; mt < 4; ++mt) {
        float s00 = 0.f, s01 = 0.f, s10 = 0.f, s11 = 0.f;
        #pragma unroll
        for (int n8 = 0; n8 < 2; ++n8) {
            const int n = nbase + wn * 16 + n8 * 8 + qlane * 2;
            const float b0 = __ldg(g_bias + n),  b1 = __ldg(g_bias + n + 1);
            const float u0 = __ldg(g_wc0 + n),   u1 = __ldg(g_wc0 + n + 1);
            const float v0 = __ldg(g_wc1 + n),   v1 = __ldg(g_wc1 + n + 1);
            float y;
            y = acc[mt][n8][0] + b0; y = (y > 0.f) ? y : 0.01f * y; s00 = fmaf(y, u0, s00); s01 = fmaf(y, v0, s01);
            y = acc[mt][n8][1] + b1; y = (y > 0.f) ? y : 0.01f * y; s00 = fmaf(y, u1, s00); s01 = fmaf(y, v1, s01);
            y = acc[mt][n8][2] + b0; y = (y > 0.f) ? y : 0.01f * y; s10 = fmaf(y, u0, s10); s11 = fmaf(y, v0, s11);
            y = acc[mt][n8][3] + b1; y = (y > 0.f) ? y : 0.01f * y; s10 = fmaf(y, u1, s10); s11 = fmaf(y, v1, s11);
        }
        s00 += __shfl_xor_sync(0xFFFFFFFF, s00, 1); s00 += __shfl_xor_sync(0xFFFFFFFF, s00, 2);
        s01 += __shfl_xor_sync(0xFFFFFFFF, s01, 1); s01 += __shfl_xor_sync(0xFFFFFFFF, s01, 2);
        s10 += __shfl_xor_sync(0xFFFFFFFF, s10, 1); s10 += __shfl_xor_sync(0xFFFFFFFF, s10, 2);
        s11 += __shfl_xor_sync(0xFFFFFFFF, s11, 1); s11 += __shfl_xor_sync(0xFFFFFFFF, s11, 2);
        if (qlane == 0) {
            const int row = wm * 64 + mt * 16 + quad;
            atomicAdd(&s_red[row].x,     s00);
            atomicAdd(&s_red[row].y,     s01);
            atomicAdd(&s_red[row + 8].x, s10);
            atomicAdd(&s_red[row + 8].y, s11);
        }
    }
    __syncthreads();
    if (tid < BM) {
        g_part[(size_t)(rbase + tid) * 8 + blockIdx.x] = s_red[tid];
    }
}

// ============================================================================
// Pack: sum 8 per-ntile partials per row -> dep(+bc) / head (deterministic)
// ============================================================================
__global__ __launch_bounds__(256) void pack_kernel(const float* __restrict__ bc)
{
    const int bi = blockIdx.x * 256 + threadIdx.x;     // 0..16383
    const float2* p = g_part + (size_t)bi * 8;
    float dx = 0.f, dy = 0.f, hx = 0.f, hy = 0.f;
    #pragma unroll
    for (int i = 0; i < 4; ++i) { const float2 v = p[i];     dx += v.x; dy += v.y; }
    #pragma unroll
    for (int i = 0; i < 4; ++i) { const float2 v = p[i + 4]; hx += v.x; hy += v.y; }
    g_dpack[bi] = make_float2(dx + __ldg(bc + 0), dy + __ldg(bc + 1));
    g_hpack[bi] = make_float2(hx, hy);
}

// ============================================================================
// Broadcast: out[b,i,j,c] = dpack[b,i,c] + hpack[b,j,c]  (coalesced 16B/16B)
// ============================================================================
__global__ __launch_bounds__(128) void bcast_kernel(float4* __restrict__ out)
{
    const int bi = blockIdx.x;              // b*1024 + i
    const int b  = bi >> 10;
    const float2 d = g_dpack[bi];
    const float4* hp = reinterpret_cast<const float4*>(g_hpack + ((size_t)b << 10));
    float4* o = out + (size_t)bi * 512;
    const int t = threadIdx.x;              // 0..127, each covers 8 j's = 4 float4
    #pragma unroll
    for (int k = 0; k < 4; ++k) {
        const float4 h = __ldg(hp + t * 4 + k);
        o[t * 4 + k] = make_float4(d.x + h.x, d.y + h.y, d.x + h.z, d.y + h.w);
    }
}

// ============================================================================
// Launch
// ============================================================================
extern "C" void kernel_launch(void* const* d_in, const int* in_sizes, int n_in,
                              void* d_out, int out_size)
{
    const float* H  = (const float*)d_in[0];
    const float* Wd = (const float*)d_in[1];
    const float* bd = (const float*)d_in[2];
    const float* Wh = (const float*)d_in[3];
    const float* bh = (const float*)d_in[4];
    const float* Wc = (const float*)d_in[5];
    const float* bc = (const float*)d_in[6];
    float* out = (float*)d_out;

    prep_kernel<<<NPAD, 256>>>(Wd, Wh, bd, bh, Wc);
    asplit_kernel<<<(BROWS * DK / 4) / 256, 256>>>((const float4*)H);

    cudaFuncSetAttribute(gemm_kernel, cudaFuncAttributeMaxDynamicSharedMemorySize, SMEM_BYTES);
    gemm_kernel<<<dim3(NPAD / BN, BROWS / BM), 512, SMEM_BYTES>>>();

    pack_kernel<<<BROWS / 256, 256>>>(bc);
    bcast_kernel<<<BROWS, 128>>>((float4*)out);
}